// round 1
// baseline (speedup 1.0000x reference)
#include <cuda_runtime.h>
#include <cuda_bf16.h>
#include <math.h>

// Problem constants
#define S_LEN 1024
#define BATCH 4
#define DMODEL 1024
#define NHEAD 16
#define HDIM 64
#define M4 4096          // BATCH * S_LEN
#define DFF 4096
#define NREL 101         // 2*MAXREL+1
#define ASTRIDE 1152     // 1024 p + 101 bucket + 27 zero pad
#define KEXT 1125        // 1024 + 101

// ---------------- scratch (device globals; no allocations allowed) ----------
__device__ float g_hn  [M4 * DMODEL];          // rmsnorm(x) in [B,S,D] order
__device__ float g_q   [M4 * DMODEL];
__device__ float g_k   [M4 * DMODEL];
__device__ float g_v   [M4 * DMODEL];
__device__ float g_qrel[64 * 1024 * NREL];     // [bh, q, r]
__device__ float g_attn[75497472];             // [bh, q, ASTRIDE] = 64*1024*1152
__device__ float g_o   [M4 * DMODEL];          // attention head outputs [B,S,D]
__device__ float g_h2  [M4 * DMODEL];          // h + attn_out
__device__ float g_ffin[M4 * DMODEL];          // rmsnorm(h2)
__device__ float g_gelu[(size_t)M4 * DFF];     // gelu(ff @ W_in^T + b_in)

// ---------------- helpers ----------------------------------------------------
__device__ __forceinline__ float gelu_f(float x) {
    return 0.5f * x * (1.0f + erff(x * 0.70710678118654752f));
}

// 256-thread block reduce (8 warps). domax: true -> max, false -> sum.
__device__ __forceinline__ float blk_reduce(float v, float* red, bool domax) {
    #pragma unroll
    for (int o = 16; o > 0; o >>= 1) {
        float u = __shfl_xor_sync(0xffffffffu, v, o);
        v = domax ? fmaxf(v, u) : (v + u);
    }
    __syncthreads();
    if ((threadIdx.x & 31) == 0) red[threadIdx.x >> 5] = v;
    __syncthreads();
    float t = red[0];
    #pragma unroll
    for (int i = 1; i < 8; i++) t = domax ? fmaxf(t, red[i]) : (t + red[i]);
    return t;
}

// ---------------- RMSNorm -----------------------------------------------------
// transpose_in = 1: input rows are [s*B+b] (x layout), output rows [b*S+s].
__global__ void __launch_bounds__(256)
rmsnorm_kernel(const float* __restrict__ in, const float* __restrict__ g,
               float* __restrict__ out, int transpose_in) {
    __shared__ float red[8];
    int row = blockIdx.x;
    int tid = threadIdx.x;
    const float* xr = in + (size_t)row * DMODEL;
    float4 v = *(const float4*)&xr[tid * 4];
    float ss = v.x * v.x + v.y * v.y + v.z * v.z + v.w * v.w;
    ss = blk_reduce(ss, red, false);
    float rms = sqrtf(ss) * 0.03125f;                // /sqrt(1024)
    float inv = 1.0f / (rms + 1e-8f);
    float4 gv = *(const float4*)&g[tid * 4];
    float4 o = make_float4(v.x * inv * gv.x, v.y * inv * gv.y,
                           v.z * inv * gv.z, v.w * inv * gv.w);
    size_t orow = row;
    if (transpose_in) {
        int s = row >> 2, b = row & 3;               // row = s*B+b
        orow = ((size_t)b << 10) + s;                // out row = b*S+s
    }
    *(float4*)&out[orow * DMODEL + tid * 4] = o;
}

// ---------------- generic SGEMM: C[M,N] = A[M,K] @ W[N,K]^T  ------------------
// EPI: 0 = +bias ; 1 = +bias,gelu ; 2 = +bias,+res[m*1024+n] ;
//      3 = +bias,+res[m*1024+n], transposed write out[(s*B+b)*D + n]
// Assumes M%128==0, N%128==0, K%16==0.
template <int EPI>
__global__ void __launch_bounds__(256)
sgemm_kernel(const float* __restrict__ A, const float* __restrict__ W,
             const float* __restrict__ bias, const float* __restrict__ res,
             float* __restrict__ C, int M, int N, int K) {
    __shared__ float sA[16][132];
    __shared__ float sB[16][132];
    int tid = threadIdx.x;
    int m0 = blockIdx.y * 128;
    int n0 = blockIdx.x * 128;
    int tx = tid & 15, ty = tid >> 4;
    int lr = tid >> 2;              // 0..63
    int lc = (tid & 3) * 4;         // 0,4,8,12
    const float* Ag = A + (size_t)(m0 + lr) * K + lc;
    const float* Wg = W + (size_t)(n0 + lr) * K + lc;
    float acc[8][8] = {};
    for (int k0 = 0; k0 < K; k0 += 16) {
        float4 a0 = *(const float4*)Ag;
        float4 a1 = *(const float4*)(Ag + (size_t)64 * K);
        float4 b0 = *(const float4*)Wg;
        float4 b1 = *(const float4*)(Wg + (size_t)64 * K);
        Ag += 16; Wg += 16;
        sA[lc + 0][lr] = a0.x; sA[lc + 1][lr] = a0.y;
        sA[lc + 2][lr] = a0.z; sA[lc + 3][lr] = a0.w;
        sA[lc + 0][lr + 64] = a1.x; sA[lc + 1][lr + 64] = a1.y;
        sA[lc + 2][lr + 64] = a1.z; sA[lc + 3][lr + 64] = a1.w;
        sB[lc + 0][lr] = b0.x; sB[lc + 1][lr] = b0.y;
        sB[lc + 2][lr] = b0.z; sB[lc + 3][lr] = b0.w;
        sB[lc + 0][lr + 64] = b1.x; sB[lc + 1][lr + 64] = b1.y;
        sB[lc + 2][lr + 64] = b1.z; sB[lc + 3][lr + 64] = b1.w;
        __syncthreads();
        #pragma unroll
        for (int kk = 0; kk < 16; kk++) {
            float4 x0 = *(const float4*)&sA[kk][ty * 8];
            float4 x1 = *(const float4*)&sA[kk][ty * 8 + 4];
            float4 y0 = *(const float4*)&sB[kk][tx * 8];
            float4 y1 = *(const float4*)&sB[kk][tx * 8 + 4];
            float av[8] = {x0.x, x0.y, x0.z, x0.w, x1.x, x1.y, x1.z, x1.w};
            float bv[8] = {y0.x, y0.y, y0.z, y0.w, y1.x, y1.y, y1.z, y1.w};
            #pragma unroll
            for (int i = 0; i < 8; i++)
                #pragma unroll
                for (int j = 0; j < 8; j++)
                    acc[i][j] += av[i] * bv[j];
        }
        __syncthreads();
    }
    // epilogue
    int nbase = n0 + tx * 8;
    float4 bz0 = *(const float4*)&bias[nbase];
    float4 bz1 = *(const float4*)&bias[nbase + 4];
    float bb[8] = {bz0.x, bz0.y, bz0.z, bz0.w, bz1.x, bz1.y, bz1.z, bz1.w};
    #pragma unroll
    for (int i = 0; i < 8; i++) {
        int m = m0 + ty * 8 + i;
        float vals[8];
        #pragma unroll
        for (int j = 0; j < 8; j++) {
            float v = acc[i][j] + bb[j];
            if (EPI == 1) v = gelu_f(v);
            vals[j] = v;
        }
        if (EPI == 2 || EPI == 3) {
            float4 r0 = *(const float4*)&res[(size_t)m * 1024 + nbase];
            float4 r1 = *(const float4*)&res[(size_t)m * 1024 + nbase + 4];
            vals[0] += r0.x; vals[1] += r0.y; vals[2] += r0.z; vals[3] += r0.w;
            vals[4] += r1.x; vals[5] += r1.y; vals[6] += r1.z; vals[7] += r1.w;
        }
        size_t obase;
        if (EPI == 3) {
            int b = m >> 10, s = m & 1023;           // m = b*S+s
            obase = ((size_t)(s * BATCH + b)) * DMODEL + nbase;
        } else {
            obase = (size_t)m * N + nbase;
        }
        *(float4*)&C[obase]     = make_float4(vals[0], vals[1], vals[2], vals[3]);
        *(float4*)&C[obase + 4] = make_float4(vals[4], vals[5], vals[6], vals[7]);
    }
}

// ---------------- qrel: qrel[bh,q,r] = q_head[q,:] . rel_k[r,:] ---------------
__global__ void __launch_bounds__(256)
qrel_kernel(const float* __restrict__ q, const float* __restrict__ relk,
            float* __restrict__ qrel) {
    __shared__ float sR[NREL][65];
    __shared__ float sQ[64][65];
    int bh = blockIdx.y;
    int b = bh >> 4, h = bh & 15;
    int q0 = blockIdx.x * 64;
    int tid = threadIdx.x;
    const float* Q = q + ((size_t)(b * S_LEN) + q0) * DMODEL + h * HDIM;
    for (int i = tid; i < NREL * 64; i += 256) {
        int r = i >> 6, d = i & 63;
        sR[r][d] = relk[i];
    }
    for (int i = tid; i < 64 * 64; i += 256) {
        int r = i >> 6, d = i & 63;
        sQ[r][d] = Q[(size_t)r * DMODEL + d];
    }
    __syncthreads();
    for (int i = tid; i < 64 * NREL; i += 256) {
        int qq = i / NREL, r = i % NREL;
        float s = 0.f;
        #pragma unroll
        for (int d = 0; d < 64; d++) s += sQ[qq][d] * sR[r][d];
        qrel[((size_t)bh * 1024 + q0 + qq) * NREL + r] = s;
    }
}

// ---------------- scores: attn[bh,q,k] = (q.k + qrel[clip(k-q)]) / 8 ----------
__global__ void __launch_bounds__(256)
score_kernel(const float* __restrict__ q, const float* __restrict__ k,
             const float* __restrict__ qrel, float* __restrict__ attn) {
    __shared__ float sQ[64][65];
    __shared__ float sK[64][65];
    int bh = blockIdx.z;
    int b = bh >> 4, h = bh & 15;
    int q0 = blockIdx.y * 64, k0 = blockIdx.x * 64;
    int tid = threadIdx.x;
    const float* Q  = q + (size_t)(b * S_LEN) * DMODEL + h * HDIM;
    const float* Kp = k + (size_t)(b * S_LEN) * DMODEL + h * HDIM;
    #pragma unroll
    for (int it = 0; it < 4; it++) {
        int r = (tid >> 4) + it * 16;
        int c = (tid & 15) * 4;
        float4 v = *(const float4*)&Q[(size_t)(q0 + r) * DMODEL + c];
        sQ[r][c] = v.x; sQ[r][c + 1] = v.y; sQ[r][c + 2] = v.z; sQ[r][c + 3] = v.w;
        float4 w = *(const float4*)&Kp[(size_t)(k0 + r) * DMODEL + c];
        sK[r][c] = w.x; sK[r][c + 1] = w.y; sK[r][c + 2] = w.z; sK[r][c + 3] = w.w;
    }
    __syncthreads();
    int tx = tid & 15, ty = tid >> 4;
    float acc[4][4] = {};
    #pragma unroll
    for (int kk = 0; kk < 64; kk++) {
        float a[4], bb[4];
        #pragma unroll
        for (int i = 0; i < 4; i++) a[i] = sQ[ty * 4 + i][kk];
        #pragma unroll
        for (int j = 0; j < 4; j++) bb[j] = sK[tx * 4 + j][kk];
        #pragma unroll
        for (int i = 0; i < 4; i++)
            #pragma unroll
            for (int j = 0; j < 4; j++)
                acc[i][j] += a[i] * bb[j];
    }
    size_t rowbase = (size_t)bh * 1024;
    #pragma unroll
    for (int i = 0; i < 4; i++) {
        int qq = q0 + ty * 4 + i;
        const float* qr = qrel + (rowbase + qq) * NREL;
        float* out = attn + (rowbase + qq) * ASTRIDE;
        #pragma unroll
        for (int j = 0; j < 4; j++) {
            int kki = k0 + tx * 4 + j;
            int d = kki - qq;
            d = min(max(d, -50), 50);
            out[kki] = (acc[i][j] + qr[d + 50]) * 0.125f;
        }
    }
}

// ---------------- softmax + relative-position buckets ------------------------
__global__ void __launch_bounds__(256)
softmax_kernel(float* __restrict__ attn) {
    __shared__ float sp[1024];
    __shared__ float red[8];
    int row = blockIdx.x;               // bh*1024 + q
    int qq = row & 1023;
    float* p = attn + (size_t)row * ASTRIDE;
    int tid = threadIdx.x;
    float4 v = *(const float4*)&p[tid * 4];
    float m = fmaxf(fmaxf(v.x, v.y), fmaxf(v.z, v.w));
    m = blk_reduce(m, red, true);
    float e0 = expf(v.x - m), e1 = expf(v.y - m);
    float e2 = expf(v.z - m), e3 = expf(v.w - m);
    float s = blk_reduce(e0 + e1 + e2 + e3, red, false);
    float inv = 1.0f / s;
    e0 *= inv; e1 *= inv; e2 *= inv; e3 *= inv;
    *(float4*)&p[tid * 4] = make_float4(e0, e1, e2, e3);
    sp[tid * 4 + 0] = e0; sp[tid * 4 + 1] = e1;
    sp[tid * 4 + 2] = e2; sp[tid * 4 + 3] = e3;
    __syncthreads();
    int lo = qq - 50, hi = qq + 50;
    float s0 = 0.f, s100 = 0.f;
    for (int kk = tid; kk < 1024; kk += 256) {
        float pv = sp[kk];
        if (kk <= lo) s0 += pv;
        if (kk >= hi) s100 += pv;
    }
    s0 = blk_reduce(s0, red, false);
    s100 = blk_reduce(s100, red, false);
    if (tid == 0) { p[1024] = s0; p[1024 + 100] = s100; }
    if (tid >= 1 && tid < 100) {
        int kk = qq + tid - 50;
        p[1024 + tid] = (kk >= 0 && kk < 1024) ? sp[kk] : 0.0f;
    }
    if (tid >= 100 && tid < 127) p[1025 + tid] = 0.0f;  // zero pad 1125..1151
}

// ---------------- AV (K-extended with rel_v) ---------------------------------
// o[b,q,h*64+d] = sum_{k<1024} p[q,k]*v[k,d] + sum_r bucket[q,r]*rel_v[r,d]
__global__ void __launch_bounds__(256)
av_kernel(const float* __restrict__ attn, const float* __restrict__ v,
          const float* __restrict__ relv, float* __restrict__ o) {
    __shared__ float sA[16][132];
    __shared__ float sB[16][68];
    int bh = blockIdx.y;
    int b = bh >> 4, h = bh & 15;
    int q0 = blockIdx.x * 128;
    int tid = threadIdx.x;
    int tx = tid & 15, ty = tid >> 4;
    int lr = tid >> 2;
    int lc = (tid & 3) * 4;
    int br = tid >> 4;               // 0..15
    int bc = (tid & 15) * 4;         // 0..60
    const float* Arow = attn + ((size_t)bh * 1024 + q0) * ASTRIDE;
    float acc[8][4] = {};
    for (int kt = 0; kt < 71; kt++) {  // ceil(1125/16)=71; cols<=1135 zero-padded
        int kk0 = kt * 16;
        float4 a0 = *(const float4*)&Arow[(size_t)lr * ASTRIDE + kk0 + lc];
        float4 a1 = *(const float4*)&Arow[(size_t)(lr + 64) * ASTRIDE + kk0 + lc];
        int kk = kk0 + br;
        float4 bv;
        if (kk < 1024)
            bv = *(const float4*)&v[((size_t)(b * S_LEN) + kk) * DMODEL + h * HDIM + bc];
        else if (kk < KEXT)
            bv = *(const float4*)&relv[(size_t)(kk - 1024) * HDIM + bc];
        else
            bv = make_float4(0.f, 0.f, 0.f, 0.f);
        sA[lc + 0][lr] = a0.x; sA[lc + 1][lr] = a0.y;
        sA[lc + 2][lr] = a0.z; sA[lc + 3][lr] = a0.w;
        sA[lc + 0][lr + 64] = a1.x; sA[lc + 1][lr + 64] = a1.y;
        sA[lc + 2][lr + 64] = a1.z; sA[lc + 3][lr + 64] = a1.w;
        *(float4*)&sB[br][bc] = bv;
        __syncthreads();
        #pragma unroll
        for (int k2 = 0; k2 < 16; k2++) {
            float4 x0 = *(const float4*)&sA[k2][ty * 8];
            float4 x1 = *(const float4*)&sA[k2][ty * 8 + 4];
            float4 y  = *(const float4*)&sB[k2][tx * 4];
            float av[8] = {x0.x, x0.y, x0.z, x0.w, x1.x, x1.y, x1.z, x1.w};
            float bw[4] = {y.x, y.y, y.z, y.w};
            #pragma unroll
            for (int i = 0; i < 8; i++)
                #pragma unroll
                for (int j = 0; j < 4; j++)
                    acc[i][j] += av[i] * bw[j];
        }
        __syncthreads();
    }
    #pragma unroll
    for (int i = 0; i < 8; i++) {
        int qq = q0 + ty * 8 + i;
        float* op = o + ((size_t)(b * S_LEN) + qq) * DMODEL + h * HDIM + tx * 4;
        *(float4*)op = make_float4(acc[i][0], acc[i][1], acc[i][2], acc[i][3]);
    }
}

// ---------------- host launch -------------------------------------------------
extern "C" void kernel_launch(void* const* d_in, const int* in_sizes, int n_in,
                              void* d_out, int out_size) {
    const float* x     = (const float*)d_in[0];
    const float* Wq    = (const float*)d_in[1];
    const float* bq    = (const float*)d_in[2];
    const float* Wk    = (const float*)d_in[3];
    const float* bk    = (const float*)d_in[4];
    const float* Wv    = (const float*)d_in[5];
    const float* bv    = (const float*)d_in[6];
    const float* Wo    = (const float*)d_in[7];
    const float* bo    = (const float*)d_in[8];
    const float* rel_k = (const float*)d_in[9];
    const float* rel_v = (const float*)d_in[10];
    const float* ga    = (const float*)d_in[11];
    const float* gf    = (const float*)d_in[12];
    const float* W_in  = (const float*)d_in[13];
    const float* b_in  = (const float*)d_in[14];
    const float* W_out = (const float*)d_in[15];
    const float* b_out = (const float*)d_in[16];
    float* out = (float*)d_out;

    float *hn, *qb, *kb, *vb, *qr, *at, *ob, *h2, *ffin, *gel;
    cudaGetSymbolAddress((void**)&hn,   g_hn);
    cudaGetSymbolAddress((void**)&qb,   g_q);
    cudaGetSymbolAddress((void**)&kb,   g_k);
    cudaGetSymbolAddress((void**)&vb,   g_v);
    cudaGetSymbolAddress((void**)&qr,   g_qrel);
    cudaGetSymbolAddress((void**)&at,   g_attn);
    cudaGetSymbolAddress((void**)&ob,   g_o);
    cudaGetSymbolAddress((void**)&h2,   g_h2);
    cudaGetSymbolAddress((void**)&ffin, g_ffin);
    cudaGetSymbolAddress((void**)&gel,  g_gelu);

    // 1. h = rmsnorm(x, g_attn), transpose [S,B,D] -> [B,S,D]
    rmsnorm_kernel<<<M4, 256>>>(x, ga, hn, 1);
    // 2. q, k, v
    dim3 g1(DMODEL / 128, M4 / 128);
    sgemm_kernel<0><<<g1, 256>>>(hn, Wq, bq, nullptr, qb, M4, DMODEL, DMODEL);
    sgemm_kernel<0><<<g1, 256>>>(hn, Wk, bk, nullptr, kb, M4, DMODEL, DMODEL);
    sgemm_kernel<0><<<g1, 256>>>(hn, Wv, bv, nullptr, vb, M4, DMODEL, DMODEL);
    // 3. qrel
    qrel_kernel<<<dim3(16, 64), 256>>>(qb, rel_k, qr);
    // 4. scores
    score_kernel<<<dim3(16, 16, 64), 256>>>(qb, kb, qr, at);
    // 5. softmax + buckets
    softmax_kernel<<<65536, 256>>>(at);
    // 6. AV (with rel_v K-extension)
    av_kernel<<<dim3(8, 64), 256>>>(at, vb, rel_v, ob);
    // 7. h2 = hn + o @ Wo^T + bo
    sgemm_kernel<2><<<g1, 256>>>(ob, Wo, bo, hn, h2, M4, DMODEL, DMODEL);
    // 8. ffin = rmsnorm(h2, g_ff)
    rmsnorm_kernel<<<M4, 256>>>(h2, gf, ffin, 0);
    // 9. gelu(ffin @ W_in^T + b_in)
    sgemm_kernel<1><<<dim3(DFF / 128, M4 / 128), 256>>>(ffin, W_in, b_in, nullptr,
                                                        gel, M4, DFF, DMODEL);
    // 10. out = h2 + gel @ W_out^T + b_out  (written back in [S,B,D] order)
    sgemm_kernel<3><<<g1, 256>>>(gel, W_out, b_out, h2, out, M4, DMODEL, DFF);
}